// round 16
// baseline (speedup 1.0000x reference)
#include <cuda_runtime.h>
#include <cuda_fp16.h>
#include <math.h>
#include <stdint.h>

// ---------------- problem constants ----------------
#define AA    64
#define EP    8
#define ETOT  512
#define HH    768
#define HI    1536
#define DD    100
#define MM    32768
#define OFF_SCORES 0
#define OFF_VGS    262144
#define OFF_IDX    262656

// ---------------- scratch (no allocs allowed) ----------------
__device__ __half  g_e16[(size_t)MM * HH];      // E fp16 [M][K]
__device__ __half  g_w1t16[(size_t)HI * HH];    // W1^T fp16 [N][K]
__device__ float   g_hown[(size_t)ETOT * HI];   // exact GELU(E_own@W1+b1) fp32
__device__ float   g_gw[HI];                    // ln_g[k] * W2[k,sel]
__device__ float   g_s1[MM];                    // per-row sum h
__device__ float   g_s2[MM];                    // per-row sum h^2
__device__ float   g_sp[MM];                    // per-row sum h*gw
__device__ float   g_sgw;
__device__ float   g_sbw;

// ---------------- helpers (base-family PTX only) ----------------
__device__ __forceinline__ uint32_t su32(const void* p) {
    uint32_t a;
    asm("{ .reg .u64 t; cvta.to.shared.u64 t, %1; cvt.u32.u64 %0, t; }"
        : "=r"(a) : "l"(p));
    return a;
}
#define CPA16(dst, src) \
    asm volatile("cp.async.cg.shared.global [%0], [%1], 16;" \
                 :: "r"(dst), "l"(src) : "memory")
#define CPA_COMMIT() asm volatile("cp.async.commit_group;" ::: "memory")
#define CPA_WAIT(n)  asm volatile("cp.async.wait_group %0;" :: "n"(n) : "memory")

#define LDSM4(r0, r1, r2, r3, addr) \
    asm volatile("ldmatrix.sync.aligned.m8n8.x4.shared.b16 {%0,%1,%2,%3}, [%4];" \
                 : "=r"(r0), "=r"(r1), "=r"(r2), "=r"(r3) : "r"(addr))

#define MMAF16(d, a0, a1, a2, a3, b0, b1) \
    asm volatile("mma.sync.aligned.m16n8k16.row.col.f32.f16.f16.f32 " \
                 "{%0,%1,%2,%3}, {%4,%5,%6,%7}, {%8,%9}, {%0,%1,%2,%3};" \
                 : "+f"((d)[0]), "+f"((d)[1]), "+f"((d)[2]), "+f"((d)[3]) \
                 : "r"(a0), "r"(a1), "r"(a2), "r"(a3), "r"(b0), "r"(b1))

__device__ __forceinline__ float gelu_exact(float x) {
    return 0.5f * x * (1.0f + erff(x * 0.7071067811865475f));
}

// ---------------- bulk GEMM tile config (unchanged; at HMMA ceiling) ------
#define BM 64
#define BN 128
#define BK 64
#define NCHUNK (HH / BK)          // 12
#define SA  0
#define SB  8192
#define STAGE 24576
#define NSTAGE 3
#define DYN_SMEM (NSTAGE * STAGE) // 72 KB -> 3 CTAs/SM

// ---------------------------------------------------------------------------
// prep_w1t: W1 [K][N] fp32 -> W1^T fp16 [N][K]
// ---------------------------------------------------------------------------
__global__ void __launch_bounds__(1024)
prep_w1t_kernel(const float* __restrict__ W1) {
    __shared__ float tile[32][33];
    const int n0 = blockIdx.x * 32;
    const int k0 = blockIdx.y * 32;
    const int tx = threadIdx.x, ty = threadIdx.y;
    tile[ty][tx] = W1[(size_t)(k0 + ty) * HI + n0 + tx];
    __syncthreads();
    g_w1t16[(size_t)(n0 + ty) * HH + k0 + tx] = __float2half(tile[tx][ty]);
}

// ---------------------------------------------------------------------------
// prep_e: E fp32 -> fp16; also zeroes the per-row reduction accumulators
// ---------------------------------------------------------------------------
__global__ void __launch_bounds__(256)
prep_e_kernel(const float* __restrict__ E) {
    const size_t i = (size_t)blockIdx.x * 256 + threadIdx.x;   // x4 floats
    float4 v = ((const float4*)E)[i];
    __half2* H = (__half2*)g_e16;
    H[i * 2]     = __floats2half2_rn(v.x, v.y);
    H[i * 2 + 1] = __floats2half2_rn(v.z, v.w);
    if (i < MM / 4) {
        const float4 z = make_float4(0.f, 0.f, 0.f, 0.f);
        ((float4*)g_s1)[i] = z;
        ((float4*)g_s2)[i] = z;
        ((float4*)g_sp)[i] = z;
    }
}

// ---------------------------------------------------------------------------
// bulk GEMM: reductions of GELU(E16 @ W1t16 + b1) fused into epilogue.
// ---------------------------------------------------------------------------
__device__ __forceinline__ void cpa_stage(uint32_t smem_u, int buf, int bm,
                                          int bn, int k0, int tid) {
    const uint32_t st = smem_u + (uint32_t)buf * STAGE;
    {
        const int row = tid >> 2;
        const int q   = tid & 3;
        const __half* ap = g_e16 + (size_t)(bm + row) * HH + k0 + q * 16;
        const uint32_t dbase = (uint32_t)row * 128;
        const int s = row & 7;
        #pragma unroll
        for (int j = 0; j < 2; j++) {
            const int c = q * 2 + j;
            CPA16(st + SA + dbase + (uint32_t)((c ^ s) * 16), ap + j * 8);
        }
    }
    {
        const int row = tid >> 1;
        const int h   = tid & 1;
        const __half* bp = g_w1t16 + (size_t)(bn + row) * HH + k0 + h * 32;
        const uint32_t dbase = (uint32_t)row * 128;
        const int s = row & 7;
        #pragma unroll
        for (int j = 0; j < 4; j++) {
            const int c = h * 4 + j;
            CPA16(st + SB + dbase + (uint32_t)((c ^ s) * 16), bp + j * 8);
        }
    }
}

__global__ void __launch_bounds__(256, 3)
gemm_hmma_kernel(const float* __restrict__ b1) {
    extern __shared__ char smem[];
    const uint32_t smem_u = su32(smem);

    const int tid = threadIdx.x;
    const int w   = tid >> 5;
    const int l   = tid & 31;
    const int wm  = w >> 2;
    const int wn  = w & 3;
    const int bn  = blockIdx.x * BN;
    const int bm  = blockIdx.y * BM;

    float acc[2][4][4];
    #pragma unroll
    for (int i = 0; i < 2; i++)
        #pragma unroll
        for (int j = 0; j < 4; j++)
            #pragma unroll
            for (int k = 0; k < 4; k++) acc[i][j][k] = 0.0f;

    const int mat  = l >> 3;
    const int rsub = l & 7;

    cpa_stage(smem_u, 0, bm, bn, 0, tid);
    CPA_COMMIT();
    cpa_stage(smem_u, 1, bm, bn, BK, tid);
    CPA_COMMIT();

    int buf = 0;
    for (int c = 0; c < NCHUNK; c++) {
        if (c + 2 < NCHUNK) {
            cpa_stage(smem_u, (c + 2) % NSTAGE, bm, bn, (c + 2) * BK, tid);
            CPA_COMMIT();
            CPA_WAIT(2);
        } else if (c + 1 < NCHUNK) {
            CPA_WAIT(1);
        } else {
            CPA_WAIT(0);
        }
        __syncthreads();

        const uint32_t stg = smem_u + (uint32_t)buf * STAGE;
        const uint32_t aB = stg + SA, bB = stg + SB;

        #pragma unroll
        for (int ks = 0; ks < 4; ks++) {
            uint32_t af[2][4], bf[2][4];

            #pragma unroll
            for (int mi = 0; mi < 2; mi++) {
                const int row = wm * 32 + mi * 16 + ((mat & 1) << 3) + rsub;
                const int ch  = ks * 2 + (mat >> 1);
                const uint32_t ad = aB + (uint32_t)(row * 128 + ((ch ^ (row & 7)) << 4));
                LDSM4(af[mi][0], af[mi][1], af[mi][2], af[mi][3], ad);
            }
            #pragma unroll
            for (int np = 0; np < 2; np++) {
                const int row = wn * 32 + np * 16 + ((mat >> 1) << 3) + rsub;
                const int ch  = ks * 2 + (mat & 1);
                const uint32_t off = (uint32_t)(row * 128 + ((ch ^ (row & 7)) << 4));
                LDSM4(bf[np][0], bf[np][1], bf[np][2], bf[np][3], bB + off);
            }
            #pragma unroll
            for (int mi = 0; mi < 2; mi++)
                #pragma unroll
                for (int ni = 0; ni < 4; ni++)
                    MMAF16(acc[mi][ni], af[mi][0], af[mi][1], af[mi][2], af[mi][3],
                           bf[ni >> 1][(ni & 1) * 2], bf[ni >> 1][(ni & 1) * 2 + 1]);
        }
        __syncthreads();
        buf = (buf + 1) % NSTAGE;
    }

    // Epilogue: bias + exact GELU in fp32 regs, per-row S1/S2/SP reduction.
    const int r0 = bm + wm * 32 + (l >> 2);
    const int c0 = bn + wn * 32 + (l & 3) * 2;
    float2 gwv[4], bbv[4];
    #pragma unroll
    for (int ni = 0; ni < 4; ni++) {
        gwv[ni] = *(const float2*)(g_gw + c0 + ni * 8);
        bbv[ni] = *(const float2*)(b1 + c0 + ni * 8);
    }
    #pragma unroll
    for (int mi = 0; mi < 2; mi++) {
        #pragma unroll
        for (int hf = 0; hf < 2; hf++) {
            const int row = r0 + mi * 16 + hf * 8;
            float s1 = 0.0f, s2 = 0.0f, sp = 0.0f;
            #pragma unroll
            for (int ni = 0; ni < 4; ni++) {
                const float h0 = gelu_exact(acc[mi][ni][hf * 2 + 0] + bbv[ni].x);
                const float h1 = gelu_exact(acc[mi][ni][hf * 2 + 1] + bbv[ni].y);
                s1 += h0 + h1;
                s2 = fmaf(h0, h0, fmaf(h1, h1, s2));
                sp = fmaf(h0, gwv[ni].x, fmaf(h1, gwv[ni].y, sp));
            }
            s1 += __shfl_xor_sync(0xFFFFFFFFu, s1, 1);
            s1 += __shfl_xor_sync(0xFFFFFFFFu, s1, 2);
            s2 += __shfl_xor_sync(0xFFFFFFFFu, s2, 1);
            s2 += __shfl_xor_sync(0xFFFFFFFFu, s2, 2);
            sp += __shfl_xor_sync(0xFFFFFFFFu, sp, 1);
            sp += __shfl_xor_sync(0xFFFFFFFFu, sp, 2);
            if ((l & 3) == 0) {
                atomicAdd(&g_s1[row], s1);
                atomicAdd(&g_s2[row], s2);
                atomicAdd(&g_sp[row], sp);
            }
        }
    }
}

// ---------------------------------------------------------------------------
// final: scores[row] from (S1,S2,SP); replicated 8x along k
// ---------------------------------------------------------------------------
__global__ void __launch_bounds__(256)
final_kernel(float* __restrict__ out) {
    const int r = blockIdx.x * 256 + threadIdx.x;   // < MM
    const float S1 = g_s1[r];
    const float S2 = g_s2[r];
    const float SP = g_sp[r];
    const float mu = S1 * (1.0f / HI);
    const float var = S2 * (1.0f / HI) - mu * mu;
    const float rstd = rsqrtf(var + 1e-12f);
    const float v = rstd * (SP - mu * g_sgw) + g_sbw;

    const int a = r >> 9;
    const int e = r & 511;
    const int m = e >> 3;
    const int j = e & 7;
    const int base = (((a * AA) + m) * EP + j) * EP;
    float4 vv = make_float4(v, v, v, v);
    *(float4*)&out[OFF_SCORES + base]     = vv;
    *(float4*)&out[OFF_SCORES + base + 4] = vv;
}

// ---------------------------------------------------------------------------
// own_gemm: exact fp32  g_hown = GELU(E_own @ W1 + b1)  [512 x 1536], K=768
// ---------------------------------------------------------------------------
__global__ void __launch_bounds__(256)
own_gemm_kernel(const float* __restrict__ E, const float* __restrict__ W1,
                const float* __restrict__ b1) {
    __shared__ float As[16][64];
    __shared__ float Bs[16][68];
    const int tid = threadIdx.x;
    const int bn = blockIdx.x * 64;
    const int bm = blockIdx.y * 64;
    const int tr = (tid >> 4) * 4;
    const int tc = (tid & 15) * 4;

    float acc[4][4];
    #pragma unroll
    for (int i = 0; i < 4; i++)
        #pragma unroll
        for (int j = 0; j < 4; j++) acc[i][j] = 0.0f;

    const int arow = tid >> 2;
    const int acol = (tid & 3) * 4;
    const int brow = tid >> 4;
    const int bcol = (tid & 15) * 4;
    const int e = bm + arow;
    const size_t asrc = ((size_t)(e >> 3) * ETOT + e) * HH;

    for (int k0 = 0; k0 < HH; k0 += 16) {
        float4 av = *(const float4*)(E + asrc + k0 + acol);
        As[acol + 0][arow] = av.x;
        As[acol + 1][arow] = av.y;
        As[acol + 2][arow] = av.z;
        As[acol + 3][arow] = av.w;
        float4 bv = *(const float4*)(W1 + (size_t)(k0 + brow) * HI + bn + bcol);
        *(float4*)&Bs[brow][bcol] = bv;
        __syncthreads();

        #pragma unroll
        for (int kk = 0; kk < 16; kk++) {
            float a[4], b[4];
            #pragma unroll
            for (int i = 0; i < 4; i++) a[i] = As[kk][tr + i];
            #pragma unroll
            for (int j = 0; j < 4; j++) b[j] = Bs[kk][tc + j];
            #pragma unroll
            for (int i = 0; i < 4; i++)
                #pragma unroll
                for (int j = 0; j < 4; j++)
                    acc[i][j] = fmaf(a[i], b[j], acc[i][j]);
        }
        __syncthreads();
    }

    #pragma unroll
    for (int i = 0; i < 4; i++) {
        #pragma unroll
        for (int j = 0; j < 4; j++) {
            const int col = bn + tc + j;
            g_hown[(size_t)(bm + tr + i) * HI + col] =
                gelu_exact(acc[i][j] + b1[col]);
        }
    }
}

// ---------------------------------------------------------------------------
// own_fused: 64 blocks x 8 entities. Exact LN + logits (W2 staged in smem)
// + softmax-max/argmax. Block 63 also computes g_gw/g_sgw/g_sbw (prep2).
// dyn smem: hs[8*1536] + w2s[128*100] floats = 100352 B.
// ---------------------------------------------------------------------------
#define OWN_SMEM ((8 * HI + 128 * DD) * 4)

__global__ void __launch_bounds__(256)
own_fused_kernel(const float* __restrict__ W2, const float* __restrict__ b2,
                 const float* __restrict__ lg_, const float* __restrict__ lb_,
                 float* __restrict__ out) {
    extern __shared__ float fsm[];
    float* hs  = fsm;                 // [8][1536]
    float* w2s = fsm + 8 * HI;        // [128][100]
    __shared__ float s_red[8];
    __shared__ int   s_sel;

    const int tid  = threadIdx.x;
    const int wid  = tid >> 5;        // 0..7  -> entity slot
    const int lane = tid & 31;
    const int e0   = blockIdx.x * 8;

    // Load 8 rows of g_hown (each thread: 12 float4)
    {
        float4* hd = (float4*)hs;
        const float4* src = (const float4*)(g_hown + (size_t)e0 * HI);
        #pragma unroll
        for (int i = 0; i < 12; i++)
            hd[tid + i * 256] = src[tid + i * 256];
    }
    __syncthreads();

    // Per-warp exact two-pass LN on row wid
    {
        float* hr = hs + wid * HI;
        float s = 0.0f;
        #pragma unroll
        for (int k = lane; k < HI; k += 32) s += hr[k];
        #pragma unroll
        for (int o = 16; o > 0; o >>= 1) s += __shfl_xor_sync(0xFFFFFFFFu, s, o);
        const float mu = s * (1.0f / HI);
        float s2 = 0.0f;
        #pragma unroll
        for (int k = lane; k < HI; k += 32) { float d = hr[k] - mu; s2 = fmaf(d, d, s2); }
        #pragma unroll
        for (int o = 16; o > 0; o >>= 1) s2 += __shfl_xor_sync(0xFFFFFFFFu, s2, o);
        const float rstd = rsqrtf(s2 * (1.0f / HI) + 1e-12f);
        #pragma unroll
        for (int k = lane; k < HI; k += 32)
            hr[k] = (hr[k] - mu) * rstd * lg_[k] + lb_[k];
    }
    __syncthreads();

    // Logits: warp = entity, lane covers classes {lane, lane+32, lane+64, lane+96}
    float a0 = 0.0f, a1 = 0.0f, a2 = 0.0f, a3 = 0.0f;
    const bool v3 = (lane + 96) < DD;
    const float* hr = hs + wid * HI;

    for (int k0 = 0; k0 < HI; k0 += 128) {
        // stage W2[k0:k0+128][0:100] -> w2s (contiguous 12800 floats)
        {
            const float4* src = (const float4*)(W2 + (size_t)k0 * DD);
            float4* dst = (float4*)w2s;
            for (int i = tid; i < (128 * DD) / 4; i += 256)
                dst[i] = src[i];
        }
        __syncthreads();
        #pragma unroll 4
        for (int kk = 0; kk < 128; kk++) {
            const float a = hr[k0 + kk];
            const float* wrow = w2s + kk * DD;
            a0 = fmaf(a, wrow[lane],      a0);
            a1 = fmaf(a, wrow[lane + 32], a1);
            a2 = fmaf(a, wrow[lane + 64], a2);
            if (v3) a3 = fmaf(a, wrow[lane + 96], a3);
        }
        __syncthreads();
    }

    a0 += b2[lane];
    a1 += b2[lane + 32];
    a2 += b2[lane + 64];
    if (v3) a3 += b2[lane + 96];

    // per-lane best (first-occurrence tie-break by smaller class)
    float bv = a0; int bc = lane;
    if (a1 > bv) { bv = a1; bc = lane + 32; }
    if (a2 > bv) { bv = a2; bc = lane + 64; }
    if (v3 && a3 > bv) { bv = a3; bc = lane + 96; }
    #pragma unroll
    for (int o = 16; o > 0; o >>= 1) {
        const float ov = __shfl_xor_sync(0xFFFFFFFFu, bv, o);
        const int   oc = __shfl_xor_sync(0xFFFFFFFFu, bc, o);
        if (ov > bv || (ov == bv && oc < bc)) { bv = ov; bc = oc; }
    }

    // softmax max = 1 / sum exp(l - max)
    float se = expf(a0 - bv) + expf(a1 - bv) + expf(a2 - bv);
    if (v3) se += expf(a3 - bv);
    #pragma unroll
    for (int o = 16; o > 0; o >>= 1) se += __shfl_xor_sync(0xFFFFFFFFu, se, o);

    if (lane == 0) {
        const int e = e0 + wid;
        out[OFF_VGS + e] = 1.0f / se;
        out[OFF_IDX + e] = (float)bc;
        if (e == ETOT - 1) s_sel = bc;
    }

    // prep2 folded into the block owning entity 511
    if (blockIdx.x == 63) {
        __syncthreads();
        const int sel = s_sel;
        float sg = 0.0f, sb = 0.0f;
        #pragma unroll
        for (int i = 0; i < 6; i++) {
            const int k = tid + i * 256;
            const float w = W2[(size_t)k * DD + sel];
            const float gw = lg_[k] * w;
            g_gw[k] = gw;
            sg += gw;
            sb += lb_[k] * w;
        }
        #pragma unroll
        for (int o = 16; o > 0; o >>= 1) {
            sg += __shfl_xor_sync(0xFFFFFFFFu, sg, o);
            sb += __shfl_xor_sync(0xFFFFFFFFu, sb, o);
        }
        if (lane == 0) s_red[wid] = sg;
        __syncthreads();
        if (tid == 0) {
            float a = 0.0f;
            #pragma unroll
            for (int w = 0; w < 8; w++) a += s_red[w];
            g_sgw = a;
        }
        __syncthreads();
        if (lane == 0) s_red[wid] = sb;
        __syncthreads();
        if (tid == 0) {
            float b = 0.0f;
            #pragma unroll
            for (int w = 0; w < 8; w++) b += s_red[w];
            g_sbw = b + b2[sel];
        }
    }
}

// ---------------------------------------------------------------------------
// launch: E, W1, b1, ln_g, ln_b, W2, b2, entity_count
// ---------------------------------------------------------------------------
extern "C" void kernel_launch(void* const* d_in, const int* in_sizes, int n_in,
                              void* d_out, int out_size) {
    const float* E    = (const float*)d_in[0];
    const float* W1   = (const float*)d_in[1];
    const float* b1   = (const float*)d_in[2];
    const float* ln_g = (const float*)d_in[3];
    const float* ln_b = (const float*)d_in[4];
    const float* W2   = (const float*)d_in[5];
    const float* b2   = (const float*)d_in[6];
    float* out = (float*)d_out;

    cudaFuncSetAttribute(gemm_hmma_kernel,
                         cudaFuncAttributeMaxDynamicSharedMemorySize, DYN_SMEM);
    cudaFuncSetAttribute(own_fused_kernel,
                         cudaFuncAttributeMaxDynamicSharedMemorySize, OWN_SMEM);

    // prep (inputs only); prep_e also zeroes the reduction buffers
    dim3 pb(32, 32);
    dim3 pg(HI / 32, HH / 32);                   // (48, 24)
    prep_w1t_kernel<<<pg, pb>>>(W1);
    prep_e_kernel<<<(MM * HH / 4) / 256, 256>>>(E);

    // exact own-rows path (produces sel -> g_gw for the fused epilogue)
    dim3 og(HI / 64, ETOT / 64);                 // (24, 8)
    own_gemm_kernel<<<og, 256>>>(E, W1, b1);
    own_fused_kernel<<<ETOT / 8, 256, OWN_SMEM>>>(W2, b2, ln_g, ln_b, out);

    // bulk fp16 path with fused per-row reductions
    dim3 gg(HI / BN, MM / BM);                   // (12, 512)
    gemm_hmma_kernel<<<gg, 256, DYN_SMEM>>>(b1);

    // scores from reductions
    final_kernel<<<MM / 256, 256>>>(out);
}